// round 11
// baseline (speedup 1.0000x reference)
#include <cuda_runtime.h>
#include <cuda_bf16.h>

#define D        512
#define NTAU     100
#define HSLOTS   128                 // ring; tag gating + skew<=1 => overwrite-safe
#define CTAS     32
#define ROWS     16                  // compute warps (rows) per CTA
#define THREADS  ((ROWS + 1) * 32)   // 544: 16 compute warps + 1 poller warp

// Tagged state ring: word = {hi32: tag = step+1, lo32: float x}.
// Relaxed-atomic b64 => single-copy atomic (no tag/payload tearing; proven R6/R8/R9).
__device__ unsigned long long g_tag[HSLOTS * D];

__device__ __forceinline__ unsigned long long ld_tag(const unsigned long long* p) {
    unsigned long long v;
    asm volatile("ld.relaxed.gpu.global.b64 %0, [%1];" : "=l"(v) : "l"(p) : "memory");
    return v;
}
__device__ __forceinline__ void st_tag(unsigned long long* p, unsigned long long v) {
    asm volatile("st.relaxed.gpu.global.b64 [%0], %1;" :: "l"(p), "l"(v) : "memory");
}
// Payload-only read (low 4B of the little-endian 8B word). .cg never fills L1.
__device__ __forceinline__ float ld_payload(const unsigned long long* p) {
    float v;
    asm volatile("ld.global.cg.f32 %0, [%1];" : "=f"(v) : "l"(p) : "memory");
    return v;
}

// smem seq flag: release-store by poller, acquire-load spin by consumers.
__device__ __forceinline__ void st_seq(int* p, int v) {
    asm volatile("st.release.cta.shared.b32 [%0], %1;"
                 :: "r"((unsigned)__cvta_generic_to_shared(p)), "r"(v) : "memory");
}
__device__ __forceinline__ int ld_seq(const int* p) {
    int v;
    asm volatile("ld.acquire.cta.shared.b32 %0, [%1];"
                 : "=r"(v) : "r"((unsigned)__cvta_generic_to_shared(p)) : "memory");
    return v;
}

// fast tanh: 1 - 2/(exp(2z)+1). MUFU.EX2 + approx div, ~70 cyc, abs err ~1e-6.
// Saturation exact: z>>0 -> e=inf -> 1;  z<<0 -> e=0 -> -1.
__device__ __forceinline__ float tanh_fast(float z) {
    const float e = __expf(2.0f * z);
    return 1.0f - __fdividef(2.0f, e + 1.0f);
}

__global__ void reset_kernel() {       // <<<256, 256>>> covers HSLOTS*D words
    g_tag[blockIdx.x * blockDim.x + threadIdx.x] = 0ULL;
}

__global__ void __launch_bounds__(THREADS, 1) ndde_kernel(
    const float* __restrict__ x0,
    const float* __restrict__ tau,
    const float* __restrict__ W1,
    const float* __restrict__ W2,
    const float* __restrict__ b,
    float* __restrict__ out,
    int N)
{
    __shared__ __align__(16) float sx[2][D];   // double-buffered x_j tile
    __shared__ int seq;                        // tile sequence flag

    const int  lane = threadIdx.x & 31;
    const int  warp = threadIdx.x >> 5;
    const bool comp = (warp < ROWS);
    const int  row  = blockIdx.x * ROWS + warp;  // valid when comp
    const long NP1  = (long)N + 1;

    if (threadIdx.x == 0) seq = 0;
    __syncthreads();                           // one-time init of seq

    if (!comp) {
        // ================= POLLER WARP =================
        // Software-pipelined parallel retry: a second blast round is ALWAYS in
        // flight, so discovery granularity is the check-loop length (~100 cyc)
        // instead of a full L2 round-trip. Validated payloads go straight to
        // the smem tile; seq release-store publishes the tile to consumers.
        for (int j = 0; j < N; ++j) {
            const unsigned long long* xs = &g_tag[(size_t)(j & (HSLOTS - 1)) * D];
            const unsigned need = (unsigned)(j + 1);
            float* tile = sx[j & 1];
            unsigned long long sA[16], sB[16];
            unsigned valid = 0;

            #pragma unroll
            for (int i = 0; i < 16; ++i) sA[i] = ld_tag(xs + lane + 32 * i);
            #pragma unroll
            for (int i = 0; i < 16; ++i) sB[i] = ld_tag(xs + lane + 32 * i);

            for (;;) {
                #pragma unroll
                for (int i = 0; i < 16; ++i)     // consume round A
                    if (!(valid & (1u << i)) && (unsigned)(sA[i] >> 32) >= need) {
                        tile[lane + 32 * i] = __uint_as_float((unsigned)sA[i]);
                        valid |= 1u << i;
                    }
                if (valid == 0xFFFFu) break;
                #pragma unroll
                for (int i = 0; i < 16; ++i)     // reissue A (round k+2)
                    if (!(valid & (1u << i))) sA[i] = ld_tag(xs + lane + 32 * i);
                #pragma unroll
                for (int i = 0; i < 16; ++i)     // consume round B
                    if (!(valid & (1u << i)) && (unsigned)(sB[i] >> 32) >= need) {
                        tile[lane + 32 * i] = __uint_as_float((unsigned)sB[i]);
                        valid |= 1u << i;
                    }
                if (valid == 0xFFFFu) break;
                #pragma unroll
                for (int i = 0; i < 16; ++i)     // reissue B
                    if (!(valid & (1u << i))) sB[i] = ld_tag(xs + lane + 32 * i);
            }
            if (lane == 0) st_seq(&seq, j + 1);  // release tile j
        }
        return;
    }

    // ================= COMPUTE WARPS (one row each) =================
    // publish x_0 FIRST so peers can start while we load weights
    float x_r = __ldg(x0 + row);
    if (lane == 0) {
        st_tag(&g_tag[row],
               (1ULL << 32) | (unsigned long long)__float_as_uint(x_r));
        out[(long)row * NP1] = x_r;
    }

    float4 w1q[4];      // float4 layout: k = 128g + 4*lane + c   (x path, smem)
    float  w2r[16];     // strided layout: k = lane + 32*i        (y path, gmem)
    const float4* W1v = (const float4*)(W1 + (long)row * D);
    #pragma unroll
    for (int g = 0; g < 4; ++g) w1q[g] = __ldg(W1v + g * 32 + lane);
    #pragma unroll
    for (int i = 0; i < 16; ++i) w2r[i] = W2[(long)row * D + lane + 32 * i];

    float acc_y0 = 0.0f;
    #pragma unroll
    for (int i = 0; i < 16; ++i)       // W2·x0 partial (y for j < NTAU)
        acc_y0 = fmaf(w2r[i], __ldg(x0 + lane + 32 * i), acc_y0);

    const float dt  = 0.01f * __ldg(tau);
    const float b_r = __ldg(b + row);

    float acc_y = acc_y0;   // per-lane partial of W2·y_j for upcoming step j
    for (int j = 0; j < N; ++j) {
        while (ld_seq(&seq) < j + 1) { }         // fine-grained tile wait

        // ---- acc = W1[row]·x_j + acc_y  (smem x, dual accumulators) ----
        const float4* xv = (const float4*)sx[j & 1];
        float4 xq[4];
        #pragma unroll
        for (int g = 0; g < 4; ++g) xq[g] = xv[g * 32 + lane];
        float a0 = acc_y, a1 = 0.0f;
        #pragma unroll
        for (int g = 0; g < 4; ++g) {
            a0 = fmaf(w1q[g].x, xq[g].x, a0);
            a1 = fmaf(w1q[g].y, xq[g].y, a1);
            a0 = fmaf(w1q[g].z, xq[g].z, a0);
            a1 = fmaf(w1q[g].w, xq[g].w, a1);
        }
        float acc = a0 + a1;
        #pragma unroll
        for (int off = 16; off; off >>= 1)
            acc += __shfl_xor_sync(0xffffffffu, acc, off);

        // ---- update + publish x_{j+1} (one 8B relaxed store, tag j+2) ----
        if (lane == 0) {
            x_r = fmaf(dt, tanh_fast(acc + b_r), x_r);
            st_tag(&g_tag[(size_t)((j + 1) & (HSLOTS - 1)) * D + row],
                   ((unsigned long long)(unsigned)(j + 2) << 32) |
                   (unsigned long long)__float_as_uint(x_r));
        }

        // ---- tail (overlaps poller's next discovery): W2·y + out store ----
        const int jn = j + 1;
        if (jn >= NTAU) {
            const unsigned long long* ys =
                &g_tag[(size_t)((jn - NTAU) & (HSLOTS - 1)) * D];
            float y0 = 0.0f, y1 = 0.0f;
            #pragma unroll
            for (int i = 0; i < 16; ++i) {
                const float yv = ld_payload(ys + lane + 32 * i);
                if (i & 1) y1 = fmaf(w2r[i], yv, y1);
                else       y0 = fmaf(w2r[i], yv, y0);
            }
            acc_y = y0 + y1;
        } else {
            acc_y = acc_y0;
        }

        if (lane == 0)
            out[(long)row * NP1 + (j + 1)] = x_r;
    }
}

extern "C" void kernel_launch(void* const* d_in, const int* in_sizes, int n_in,
                              void* d_out, int out_size) {
    const float* x0  = (const float*)d_in[0];
    const float* tau = (const float*)d_in[1];
    const float* W1  = (const float*)d_in[2];
    const float* W2  = (const float*)d_in[3];
    const float* b   = (const float*)d_in[4];
    float* out = (float*)d_out;

    const int N = out_size / D - 1;    // out is [D, N+1]

    reset_kernel<<<256, 256>>>();      // zero tags (graph-replay determinism)
    ndde_kernel<<<CTAS, THREADS>>>(x0, tau, W1, W2, b, out, N);
}

// round 12
// speedup vs baseline: 1.4108x; 1.4108x over previous
#include <cuda_runtime.h>
#include <cuda_bf16.h>

#define D        512
#define NTAU     100
#define HSLOTS   128                 // ring; tag gating + skew<=1 => overwrite-safe
#define CTAS     32
#define ROWS     16                  // compute warps (rows) per CTA
#define THREADS  ((ROWS + 1) * 32)   // 544: 16 compute warps + 1 poller warp

// Tagged state ring: word = {hi32: tag = step+1, lo32: float x}.
// Relaxed-atomic b64 => single-copy atomic (no tag/payload tearing; proven R6/R8/R9).
__device__ unsigned long long g_tag[HSLOTS * D];

__device__ __forceinline__ unsigned long long ld_tag(const unsigned long long* p) {
    unsigned long long v;
    asm volatile("ld.relaxed.gpu.global.b64 %0, [%1];" : "=l"(v) : "l"(p) : "memory");
    return v;
}
__device__ __forceinline__ void st_tag(unsigned long long* p, unsigned long long v) {
    asm volatile("st.relaxed.gpu.global.b64 [%0], %1;" :: "l"(p), "l"(v) : "memory");
}
// Payload-only read (low 4B of the little-endian 8B word). .cg never fills L1.
__device__ __forceinline__ float ld_payload(const unsigned long long* p) {
    float v;
    asm volatile("ld.global.cg.f32 %0, [%1];" : "=f"(v) : "l"(p) : "memory");
    return v;
}

// Producer/consumer named barrier: poller arrives (never waits), compute syncs.
// Passive wait — parks warps, no MIO/issue-slot burn (R11 lesson).
#define TILE_ARRIVE() asm volatile("bar.arrive 1, %0;" :: "n"(THREADS) : "memory")
#define TILE_WAIT()   asm volatile("bar.sync   1, %0;" :: "n"(THREADS) : "memory")

// fast tanh: 1 - 2/(exp(2z)+1). MUFU.EX2 + approx div, ~70 cyc vs ~200 for tanhf.
// Saturation exact: z>>0 -> e=inf -> 1;  z<<0 -> e=0 -> -1. abs err ~1e-6.
__device__ __forceinline__ float tanh_fast(float z) {
    const float e = __expf(2.0f * z);
    return 1.0f - __fdividef(2.0f, e + 1.0f);
}

__global__ void reset_kernel() {       // <<<256, 256>>> covers HSLOTS*D words
    g_tag[blockIdx.x * blockDim.x + threadIdx.x] = 0ULL;
}

__global__ void __launch_bounds__(THREADS, 1) ndde_kernel(
    const float* __restrict__ x0,
    const float* __restrict__ tau,
    const float* __restrict__ W1,
    const float* __restrict__ W2,
    const float* __restrict__ b,
    float* __restrict__ out,
    int N)
{
    __shared__ __align__(16) float sx[2][D];   // double-buffered x_j tile

    const int  lane = threadIdx.x & 31;
    const int  warp = threadIdx.x >> 5;
    const bool comp = (warp < ROWS);
    const int  row  = blockIdx.x * ROWS + warp;  // valid when comp
    const long NP1  = (long)N + 1;

    if (!comp) {
        // ================= POLLER WARP =================
        // Parallel retry: each round reloads ALL stale words concurrently
        // (independent loads) — no serial spin chains (R9 lesson).
        for (int j = 0; j < N; ++j) {
            const unsigned long long* xs = &g_tag[(size_t)(j & (HSLOTS - 1)) * D];
            const unsigned need = (unsigned)(j + 1);
            unsigned long long v[16];
            unsigned stale = 0xFFFFu;
            do {
                #pragma unroll
                for (int i = 0; i < 16; ++i)
                    if (stale & (1u << i))
                        v[i] = ld_tag(xs + lane + 32 * i);   // parallel reloads
                #pragma unroll
                for (int i = 0; i < 16; ++i)
                    if ((stale & (1u << i)) && (unsigned)(v[i] >> 32) >= need)
                        stale &= ~(1u << i);
            } while (stale);
            #pragma unroll
            for (int i = 0; i < 16; ++i)
                sx[j & 1][lane + 32 * i] = __uint_as_float((unsigned)v[i]);
            TILE_ARRIVE();                       // release tile j to compute
        }
        return;
    }

    // ================= COMPUTE WARPS (one row each) =================
    // publish x_0 FIRST so peers can start while we load weights
    float x_r = __ldg(x0 + row);
    if (lane == 0) {
        st_tag(&g_tag[row],
               (1ULL << 32) | (unsigned long long)__float_as_uint(x_r));
        out[(long)row * NP1] = x_r;
    }

    float4 w1q[4];      // float4 layout: k = 128g + 4*lane + c   (x path, smem)
    float  w2r[16];     // strided layout: k = lane + 32*i        (y path, gmem)
    const float4* W1v = (const float4*)(W1 + (long)row * D);
    #pragma unroll
    for (int g = 0; g < 4; ++g) w1q[g] = __ldg(W1v + g * 32 + lane);
    #pragma unroll
    for (int i = 0; i < 16; ++i) w2r[i] = W2[(long)row * D + lane + 32 * i];

    float acc_y0 = 0.0f;
    #pragma unroll
    for (int i = 0; i < 16; ++i)       // W2·x0 partial (y for j < NTAU)
        acc_y0 = fmaf(w2r[i], __ldg(x0 + lane + 32 * i), acc_y0);

    const float dt  = 0.01f * __ldg(tau);
    const float b_r = __ldg(b + row);

    float acc_y = acc_y0;   // per-lane partial of W2·y_j for upcoming step j
    for (int j = 0; j < N; ++j) {
        TILE_WAIT();                             // wait ONLY for the poller

        // ---- acc = W1[row]·x_j + acc_y  (smem x, dual accumulators) ----
        const float4* xv = (const float4*)sx[j & 1];
        float4 xq[4];
        #pragma unroll
        for (int g = 0; g < 4; ++g) xq[g] = xv[g * 32 + lane];
        float a0 = acc_y, a1 = 0.0f;
        #pragma unroll
        for (int g = 0; g < 4; ++g) {
            a0 = fmaf(w1q[g].x, xq[g].x, a0);
            a1 = fmaf(w1q[g].y, xq[g].y, a1);
            a0 = fmaf(w1q[g].z, xq[g].z, a0);
            a1 = fmaf(w1q[g].w, xq[g].w, a1);
        }
        float acc = a0 + a1;
        #pragma unroll
        for (int off = 16; off; off >>= 1)
            acc += __shfl_xor_sync(0xffffffffu, acc, off);

        // ---- update + publish x_{j+1} (one 8B relaxed store, tag j+2) ----
        if (lane == 0) {
            x_r = fmaf(dt, tanh_fast(acc + b_r), x_r);
            st_tag(&g_tag[(size_t)((j + 1) & (HSLOTS - 1)) * D + row],
                   ((unsigned long long)(unsigned)(j + 2) << 32) |
                   (unsigned long long)__float_as_uint(x_r));
        }

        // ---- tail (overlaps poller's next discovery): W2·y + out store ----
        const int jn = j + 1;
        if (jn >= NTAU) {
            const unsigned long long* ys =
                &g_tag[(size_t)((jn - NTAU) & (HSLOTS - 1)) * D];
            float y0 = 0.0f, y1 = 0.0f;
            #pragma unroll
            for (int i = 0; i < 16; ++i) {
                const float yv = ld_payload(ys + lane + 32 * i);
                if (i & 1) y1 = fmaf(w2r[i], yv, y1);
                else       y0 = fmaf(w2r[i], yv, y0);
            }
            acc_y = y0 + y1;
        } else {
            acc_y = acc_y0;
        }

        if (lane == 0)
            out[(long)row * NP1 + (j + 1)] = x_r;
    }
}

extern "C" void kernel_launch(void* const* d_in, const int* in_sizes, int n_in,
                              void* d_out, int out_size) {
    const float* x0  = (const float*)d_in[0];
    const float* tau = (const float*)d_in[1];
    const float* W1  = (const float*)d_in[2];
    const float* W2  = (const float*)d_in[3];
    const float* b   = (const float*)d_in[4];
    float* out = (float*)d_out;

    const int N = out_size / D - 1;    // out is [D, N+1]

    reset_kernel<<<256, 256>>>();      // zero tags (graph-replay determinism)
    ndde_kernel<<<CTAS, THREADS>>>(x0, tau, W1, W2, b, out, N);
}